// round 1
// baseline (speedup 1.0000x reference)
#include <cuda_runtime.h>
#include <cstdint>

#define B_    32
#define T_    512
#define D_    512
#define H_    512
#define FOURH 2048
#define NCTA  64          // CTAs per direction
#define HC    8           // hidden units per CTA (512/64)
#define STRIDE 516        // padded smem stride (conflict-free)
#define SMEM_BYTES ((32*STRIDE + 32*STRIDE + 32*33) * 4)

// Scratch (static device allocations are the only legal scratch)
__device__ float g_xp[2][(size_t)B_ * T_ * FOURH];   // input projections, 2 x 128MB
__device__ float g_h[2][2][B_ * H_];                 // h state, [dir][parity]
__device__ unsigned g_count[2];
__device__ unsigned g_gen[2];

__device__ __forceinline__ float sigm(float x) { return 1.f / (1.f + __expf(-x)); }
__device__ __forceinline__ float tanh_(float x) { return 2.f / (1.f + __expf(-2.f * x)) - 1.f; }

// ---------------------------------------------------------------------------
// Phase 1: xp[dir] = x @ W[dir][:D] + b[dir]
// Classic 128x128x8 register-tiled fp32 GEMM, 256 threads, 8x8 microtile.
// M=16384, N=2048, K=512 (all divide tiles exactly — no bounds checks).
// ---------------------------------------------------------------------------
__global__ __launch_bounds__(256) void gemm_xp(
    const float* __restrict__ x,
    const float* __restrict__ Wfw, const float* __restrict__ bfw,
    const float* __restrict__ Wbw, const float* __restrict__ bbw)
{
    const int dir = blockIdx.z;
    const float* __restrict__ Wd = dir ? Wbw : Wfw;
    const float* __restrict__ bd = dir ? bbw : bfw;
    float* __restrict__ C = g_xp[dir];

    __shared__ float As[8][128];
    __shared__ float Bs[8][128];

    const int tid = threadIdx.x;
    const int m0 = blockIdx.y * 128;
    const int n0 = blockIdx.x * 128;
    const int tx = tid & 15;        // 16 cols of threads
    const int ty = tid >> 4;        // 16 rows of threads

    // A tile load: thread -> (row, 4 k's); stored transposed As[k][m]
    const int arow = tid >> 1;
    const int ak4  = (tid & 1) * 4;
    // B tile load: thread -> (k, 4 n's)
    const int bk = tid >> 5;
    const int bn = (tid & 31) * 4;

    const float* Ap = x  + (size_t)(m0 + arow) * D_ + ak4;
    const float* Bp = Wd + (size_t)bk * FOURH + n0 + bn;

    float acc[8][8];
#pragma unroll
    for (int i = 0; i < 8; i++)
#pragma unroll
        for (int j = 0; j < 8; j++) acc[i][j] = 0.f;

    for (int k0 = 0; k0 < D_; k0 += 8) {
        float4 av = *(const float4*)(Ap + k0);
        float4 bv = *(const float4*)(Bp + (size_t)k0 * FOURH);
        As[ak4 + 0][arow] = av.x;
        As[ak4 + 1][arow] = av.y;
        As[ak4 + 2][arow] = av.z;
        As[ak4 + 3][arow] = av.w;
        *(float4*)&Bs[bk][bn] = bv;
        __syncthreads();

#pragma unroll
        for (int kk = 0; kk < 8; kk++) {
            float a[8], b[8];
            *(float4*)(a + 0) = *(const float4*)&As[kk][ty * 8 + 0];
            *(float4*)(a + 4) = *(const float4*)&As[kk][ty * 8 + 4];
            *(float4*)(b + 0) = *(const float4*)&Bs[kk][tx * 8 + 0];
            *(float4*)(b + 4) = *(const float4*)&Bs[kk][tx * 8 + 4];
#pragma unroll
            for (int i = 0; i < 8; i++)
#pragma unroll
                for (int j = 0; j < 8; j++)
                    acc[i][j] = fmaf(a[i], b[j], acc[i][j]);
        }
        __syncthreads();
    }

    float bias[8];
#pragma unroll
    for (int j = 0; j < 8; j++) bias[j] = bd[n0 + tx * 8 + j];

#pragma unroll
    for (int i = 0; i < 8; i++) {
        const size_t row = (size_t)(m0 + ty * 8 + i);
        float* cp = C + row * FOURH + n0 + tx * 8;
        float4 o0, o1;
        o0.x = acc[i][0] + bias[0]; o0.y = acc[i][1] + bias[1];
        o0.z = acc[i][2] + bias[2]; o0.w = acc[i][3] + bias[3];
        o1.x = acc[i][4] + bias[4]; o1.y = acc[i][5] + bias[5];
        o1.z = acc[i][6] + bias[6]; o1.w = acc[i][7] + bias[7];
        *(float4*)(cp + 0) = o0;
        *(float4*)(cp + 4) = o1;
    }
}

// ---------------------------------------------------------------------------
// Phase 2: persistent bidirectional LSTM recurrence.
// Grid = 128 CTAs (64 per direction), 256 threads. One CTA per SM (133 KB smem)
// -> all CTAs co-resident -> global spin barrier per step per direction valid.
// Each CTA owns HC=8 hidden units; its Wh slice (512 x 32 cols) lives in smem
// for all 512 steps. h[32x512] exchanged via L2 (double-buffered by parity).
// Dot layout: lane = batch (h LDS.128 conflict-free), warp owns 4 cols
// (W LDS.128 broadcast) -> FMA-pipe-bound inner loop.
// ---------------------------------------------------------------------------
__global__ __launch_bounds__(256) void lstm_kernel(
    const float* __restrict__ Wfw, const float* __restrict__ Wbw,
    float* __restrict__ out)
{
    extern __shared__ float sm[];
    float* Wsh = sm;                 // [32 cols][STRIDE]
    float* hsh = sm + 32 * STRIDE;   // [32 b][STRIDE]
    float* zsh = sm + 64 * STRIDE;   // [32 cols][33]

    const int tid = threadIdx.x;
    const int dir = blockIdx.x / NCTA;
    const int cta = blockIdx.x % NCTA;
    const int j0  = cta * HC;
    const float* __restrict__ W  = dir ? Wbw : Wfw;
    const float* __restrict__ xp = g_xp[dir];

    // Prologue: stage Wh slice into smem. Column c = gate*8 + jj maps to
    // global column gate*H + j0 + jj of W rows [D, D+H).
    for (int idx = tid; idx < 32 * 512; idx += 256) {
        const int c = idx >> 9, k = idx & 511;
        const int gate = c >> 3, jj = c & 7;
        Wsh[c * STRIDE + k] = W[(size_t)(D_ + k) * FOURH + gate * H_ + j0 + jj];
    }

    const int warp = tid >> 5, lane = tid & 31;
    const int gate_w = warp >> 1;            // gate handled by this warp
    const int jjb    = (warp & 1) * 4;       // first unit offset of this warp
    const int b_g = tid >> 3, jj_g = tid & 7; // gate-stage role
    const int c0 = warp * 4;

    const float4* hb  = (const float4*)(hsh + lane * STRIDE);
    const float4* wp0 = (const float4*)(Wsh + (c0 + 0) * STRIDE);
    const float4* wp1 = (const float4*)(Wsh + (c0 + 1) * STRIDE);
    const float4* wp2 = (const float4*)(Wsh + (c0 + 2) * STRIDE);
    const float4* wp3 = (const float4*)(Wsh + (c0 + 3) * STRIDE);

    float cst = 0.f;   // cell state for (b_g, j0+jj_g), register-resident
    __syncthreads();

    for (int s = 0; s < T_; s++) {
        const int t = dir ? (T_ - 1 - s) : s;

        if (s > 0) {
            // Stage previous h (written to parity (s-1)&1) into smem via L2.
            const float4* src = (const float4*)(g_h[dir][(s - 1) & 1]);
#pragma unroll 4
            for (int i = tid; i < (B_ * H_) / 4; i += 256) {
                float4 v = __ldcg(src + i);
                const int bb = i >> 7, k4 = i & 127;
                *(float4*)(hsh + bb * STRIDE + k4 * 4) = v;
            }
        }
        __syncthreads();

        float a0 = 0.f, a1 = 0.f, a2 = 0.f, a3 = 0.f;
        if (s > 0) {
#pragma unroll 4
            for (int k = 0; k < 128; k++) {
                const float4 hv = hb[k];
                float4 w;
                w = wp0[k];
                a0 = fmaf(hv.x, w.x, a0); a0 = fmaf(hv.y, w.y, a0);
                a0 = fmaf(hv.z, w.z, a0); a0 = fmaf(hv.w, w.w, a0);
                w = wp1[k];
                a1 = fmaf(hv.x, w.x, a1); a1 = fmaf(hv.y, w.y, a1);
                a1 = fmaf(hv.z, w.z, a1); a1 = fmaf(hv.w, w.w, a1);
                w = wp2[k];
                a2 = fmaf(hv.x, w.x, a2); a2 = fmaf(hv.y, w.y, a2);
                a2 = fmaf(hv.z, w.z, a2); a2 = fmaf(hv.w, w.w, a2);
                w = wp3[k];
                a3 = fmaf(hv.x, w.x, a3); a3 = fmaf(hv.y, w.y, a3);
                a3 = fmaf(hv.z, w.z, a3); a3 = fmaf(hv.w, w.w, a3);
            }
        }

        // Add precomputed x-projection (bias already folded in).
        const size_t xb = ((size_t)lane * T_ + t) * FOURH + gate_w * H_ + j0 + jjb;
        a0 += __ldg(xp + xb + 0);
        a1 += __ldg(xp + xb + 1);
        a2 += __ldg(xp + xb + 2);
        a3 += __ldg(xp + xb + 3);

        zsh[(c0 + 0) * 33 + lane] = a0;
        zsh[(c0 + 1) * 33 + lane] = a1;
        zsh[(c0 + 2) * 33 + lane] = a2;
        zsh[(c0 + 3) * 33 + lane] = a3;
        __syncthreads();

        // Gate stage: thread (b_g, jj_g) gathers its 4 gates.
        const float zi = zsh[( 0 + jj_g) * 33 + b_g];
        const float zf = zsh[( 8 + jj_g) * 33 + b_g];
        const float zo = zsh[(16 + jj_g) * 33 + b_g];
        const float zg = zsh[(24 + jj_g) * 33 + b_g];
        const float ig = sigm(zi), fg = sigm(zf), og = sigm(zo), gg = tanh_(zg);
        cst = fmaf(fg, cst, ig * gg);
        const float hv = og * tanh_(cst);

        const int j = j0 + jj_g;
        __stcg(&g_h[dir][s & 1][b_g * H_ + j], hv);
        out[((size_t)b_g * T_ + t) * (2 * H_) + dir * H_ + j] = hv;
        __syncthreads();

        // Per-direction grid barrier (sense-reversing; launch-state safe:
        // gen is read relative, count always returns to 0).
        if (tid == 0) {
            __threadfence();
            const unsigned gen = *(volatile unsigned*)&g_gen[dir];
            const unsigned old = atomicAdd(&g_count[dir], 1);
            if (old == NCTA - 1) {
                atomicExch(&g_count[dir], 0);
                __threadfence();
                atomicAdd(&g_gen[dir], 1);
            } else {
                while (*(volatile unsigned*)&g_gen[dir] == gen) { }
            }
            __threadfence();
        }
        __syncthreads();
    }
}

// ---------------------------------------------------------------------------
// Launch: GEMM (both directions, z-grid) then persistent recurrence.
// ---------------------------------------------------------------------------
extern "C" void kernel_launch(void* const* d_in, const int* in_sizes, int n_in,
                              void* d_out, int out_size)
{
    const float* x   = (const float*)d_in[0];
    const float* Wfw = (const float*)d_in[1];
    const float* bfw = (const float*)d_in[2];
    const float* Wbw = (const float*)d_in[3];
    const float* bbw = (const float*)d_in[4];
    float* out = (float*)d_out;

    dim3 g(FOURH / 128, (B_ * T_) / 128, 2);   // 16 x 128 x 2
    gemm_xp<<<g, 256>>>(x, Wfw, bfw, Wbw, bbw);

    cudaFuncSetAttribute(lstm_kernel,
                         cudaFuncAttributeMaxDynamicSharedMemorySize, SMEM_BYTES);
    lstm_kernel<<<2 * NCTA, 256, SMEM_BYTES>>>(Wfw, Wbw, out);
}